// round 11
// baseline (speedup 1.0000x reference)
#include <cuda_runtime.h>
#include <cuda_bf16.h>
#include <cstdint>
#include <math.h>

#define NN 100000
#define EE 3200000
#define FF 128

// ---------------- static device scratch (no allocations allowed) ----------------
__device__ __nv_bfloat16 g_xb[NN * FF];   // conv2 gather source (h1*outnorm, bf16)
__device__ __nv_bfloat16 g_aggb[NN * FF]; // bf16 aggregation output (x innorm)
__device__ __nv_bfloat16 g_w1t[FF * FF];  // W1^T bf16 [n][k]
__device__ __nv_bfloat16 g_w2t[FF * FF];
__device__ __nv_bfloat16 g_wm1t[FF * FF];
__device__ __nv_bfloat16 g_wm2t[64 * FF];
__device__ float g_outnorm[NN];
__device__ float g_innorm[NN];
__device__ int   g_outdeg[NN];
__device__ int   g_indeg[NN];
__device__ int   g_rowptr[NN + 1];
__device__ int   g_cursor[NN];
__device__ int   g_partial[128];
__device__ int   g_csrc[EE];              // CSR (by dst) column indices = src nodes

// ---------------- graph preprocessing ----------------
__global__ void __launch_bounds__(256) zero_kernel() {
    int i = blockIdx.x * blockDim.x + threadIdx.x;
    if (i < NN) { g_outdeg[i] = 0; g_indeg[i] = 0; }
}

// 4 edges per thread (EE divisible by 4)
__global__ void __launch_bounds__(256) degree_kernel(const int4* __restrict__ src4, const int4* __restrict__ dst4) {
    int i = blockIdx.x * blockDim.x + threadIdx.x;
    if (i < EE / 4) {
        int4 s = src4[i], d = dst4[i];
        atomicAdd(&g_outdeg[s.x], 1); atomicAdd(&g_outdeg[s.y], 1);
        atomicAdd(&g_outdeg[s.z], 1); atomicAdd(&g_outdeg[s.w], 1);
        atomicAdd(&g_indeg[d.x], 1); atomicAdd(&g_indeg[d.y], 1);
        atomicAdd(&g_indeg[d.z], 1); atomicAdd(&g_indeg[d.w], 1);
    }
}

__global__ void __launch_bounds__(256) scan_reduce_kernel() {
    __shared__ int s[256];
    int t = threadIdx.x;
    int base = blockIdx.x * 1024;
    int v = 0;
#pragma unroll
    for (int j = 0; j < 4; j++) {
        int i = base + t + j * 256;
        if (i < NN) v += g_indeg[i];
    }
    s[t] = v;
    __syncthreads();
    for (int off = 128; off > 0; off >>= 1) {
        if (t < off) s[t] += s[t + off];
        __syncthreads();
    }
    if (t == 0) g_partial[blockIdx.x] = s[0];
}

__global__ void __launch_bounds__(128) scan_partials_kernel(int nparts) {
    __shared__ int s[128];
    int t = threadIdx.x;
    int v = (t < nparts) ? g_partial[t] : 0;
    s[t] = v;
    __syncthreads();
    for (int off = 1; off < 128; off <<= 1) {
        int u = (t >= off) ? s[t - off] : 0;
        __syncthreads();
        s[t] += u;
        __syncthreads();
    }
    if (t < nparts) g_partial[t] = s[t] - v;
}

__global__ void __launch_bounds__(1024) scan_down_kernel() {
    __shared__ int s[1024];
    int t = threadIdx.x;
    int i = blockIdx.x * 1024 + t;
    int d = (i < NN) ? g_indeg[i] : 0;
    s[t] = d;
    __syncthreads();
    for (int off = 1; off < 1024; off <<= 1) {
        int u = (t >= off) ? s[t - off] : 0;
        __syncthreads();
        s[t] += u;
        __syncthreads();
    }
    if (i < NN) {
        int rp = s[t] - d + g_partial[blockIdx.x];
        g_rowptr[i] = rp;
        g_cursor[i] = rp;
        g_innorm[i]  = rsqrtf((float)max(d, 1));
        g_outnorm[i] = rsqrtf((float)max(g_outdeg[i], 1));
    }
    if (i == 0) g_rowptr[NN] = EE;
}

__global__ void __launch_bounds__(256) fill_kernel(const int4* __restrict__ src4, const int4* __restrict__ dst4) {
    int i = blockIdx.x * blockDim.x + threadIdx.x;
    if (i < EE / 4) {
        int4 s = src4[i], d = dst4[i];
        g_csrc[atomicAdd(&g_cursor[d.x], 1)] = s.x;
        g_csrc[atomicAdd(&g_cursor[d.y], 1)] = s.y;
        g_csrc[atomicAdd(&g_cursor[d.z], 1)] = s.z;
        g_csrc[atomicAdd(&g_cursor[d.w], 1)] = s.w;
    }
}

// ---------------- weight prep: transpose + bf16 ----------------
__global__ void __launch_bounds__(256) wt_kernel(
    const float* __restrict__ W1, const float* __restrict__ W2,
    const float* __restrict__ Wm1, const float* __restrict__ Wm2) {
    int i = blockIdx.x * blockDim.x + threadIdx.x;
    if (i < 16384) {
        int k = i >> 7, n = i & 127;
        g_w1t[n * 128 + k] = __float2bfloat16(W1[i]);
    } else if (i < 32768) {
        int j = i - 16384; int k = j >> 7, n = j & 127;
        g_w2t[n * 128 + k] = __float2bfloat16(W2[j]);
    } else if (i < 49152) {
        int j = i - 32768; int k = j >> 7, n = j & 127;
        g_wm1t[n * 128 + k] = __float2bfloat16(Wm1[j]);
    } else if (i < 57344) {
        int j = i - 49152; int k = j >> 6, n = j & 63;
        g_wm2t[n * 128 + k] = __float2bfloat16(Wm2[j]);
    }
}

// ---------------- aggregation ----------------
__device__ __forceinline__ float4 bf4_to_f4(uint2 p) {
    __nv_bfloat162 b0 = *reinterpret_cast<__nv_bfloat162*>(&p.x);
    __nv_bfloat162 b1 = *reinterpret_cast<__nv_bfloat162*>(&p.y);
    float2 f0 = __bfloat1622float2(b0);
    float2 f1 = __bfloat1622float2(b1);
    return make_float4(f0.x, f0.y, f1.x, f1.y);
}

// conv1: gather fp32 x, scale by out_norm[src], fold in_norm[dst], write bf16 agg
__global__ void __launch_bounds__(256) agg1_kernel(const float4* __restrict__ X) {
    int w = (blockIdx.x * blockDim.x + threadIdx.x) >> 5;
    if (w >= NN) return;
    int lane = threadIdx.x & 31;
    int s = g_rowptr[w], e = g_rowptr[w + 1];
    float4 acc = make_float4(0.f, 0.f, 0.f, 0.f);
    int j = s;
    for (; j + 3 < e; j += 4) {
        int u0 = g_csrc[j], u1 = g_csrc[j + 1], u2 = g_csrc[j + 2], u3 = g_csrc[j + 3];
        float4 a = X[u0 * 32 + lane];
        float4 b = X[u1 * 32 + lane];
        float4 c = X[u2 * 32 + lane];
        float4 d = X[u3 * 32 + lane];
        float n0 = g_outnorm[u0], n1 = g_outnorm[u1], n2 = g_outnorm[u2], n3 = g_outnorm[u3];
        acc.x += a.x * n0 + b.x * n1 + c.x * n2 + d.x * n3;
        acc.y += a.y * n0 + b.y * n1 + c.y * n2 + d.y * n3;
        acc.z += a.z * n0 + b.z * n1 + c.z * n2 + d.z * n3;
        acc.w += a.w * n0 + b.w * n1 + c.w * n2 + d.w * n3;
    }
    for (; j < e; j++) {
        int u = g_csrc[j];
        float4 a = X[u * 32 + lane];
        float n = g_outnorm[u];
        acc.x += a.x * n; acc.y += a.y * n; acc.z += a.z * n; acc.w += a.w * n;
    }
    float inw = g_innorm[w];
    acc.x *= inw; acc.y *= inw; acc.z *= inw; acc.w *= inw;
    __nv_bfloat162 b0 = __floats2bfloat162_rn(acc.x, acc.y);
    __nv_bfloat162 b1 = __floats2bfloat162_rn(acc.z, acc.w);
    uint2 p;
    p.x = *reinterpret_cast<unsigned*>(&b0);
    p.y = *reinterpret_cast<unsigned*>(&b1);
    ((uint2*)g_aggb)[w * 32 + lane] = p;
}

// conv2: gather bf16 (pre-scaled), fold in_norm[dst], write bf16 agg; 8-edge unroll
__global__ void __launch_bounds__(256) agg2_kernel() {
    int w = (blockIdx.x * blockDim.x + threadIdx.x) >> 5;
    if (w >= NN) return;
    int lane = threadIdx.x & 31;
    int s = g_rowptr[w], e = g_rowptr[w + 1];
    const uint2* __restrict__ X = (const uint2*)g_xb;
    float4 acc = make_float4(0.f, 0.f, 0.f, 0.f);
    int j = s;
    for (; j + 7 < e; j += 8) {
        int us[8];
#pragma unroll
        for (int q = 0; q < 8; q++) us[q] = g_csrc[j + q];
        uint2 vs[8];
#pragma unroll
        for (int q = 0; q < 8; q++) vs[q] = X[us[q] * 32 + lane];
#pragma unroll
        for (int q = 0; q < 8; q++) {
            float4 a = bf4_to_f4(vs[q]);
            acc.x += a.x; acc.y += a.y; acc.z += a.z; acc.w += a.w;
        }
    }
    for (; j < e; j++) {
        float4 a = bf4_to_f4(X[g_csrc[j] * 32 + lane]);
        acc.x += a.x; acc.y += a.y; acc.z += a.z; acc.w += a.w;
    }
    float inw = g_innorm[w];
    acc.x *= inw; acc.y *= inw; acc.z *= inw; acc.w *= inw;
    __nv_bfloat162 b0 = __floats2bfloat162_rn(acc.x, acc.y);
    __nv_bfloat162 b1 = __floats2bfloat162_rn(acc.z, acc.w);
    uint2 p;
    p.x = *reinterpret_cast<unsigned*>(&b0);
    p.y = *reinterpret_cast<unsigned*>(&b1);
    ((uint2*)g_aggb)[w * 32 + lane] = p;
}

// ---------------- mma.sync fragment helpers ----------------
#define SA 136  // smem row stride in bf16 elems

__device__ __forceinline__ void mma16816(float* c, const unsigned* a, const unsigned* b) {
    asm volatile(
        "mma.sync.aligned.m16n8k16.row.col.f32.bf16.bf16.f32 "
        "{%0,%1,%2,%3}, {%4,%5,%6,%7}, {%8,%9}, {%0,%1,%2,%3};"
        : "+f"(c[0]), "+f"(c[1]), "+f"(c[2]), "+f"(c[3])
        : "r"(a[0]), "r"(a[1]), "r"(a[2]), "r"(a[3]), "r"(b[0]), "r"(b[1]));
}

// one full 128xNRx128 MMA stage from smem As/Bs into c[2][NT][4]
template <int NT>
__device__ __forceinline__ void mma_stage(const __nv_bfloat16* As, const __nv_bfloat16* Bs,
                                          int wm, int wn, int gid, int tig, float c[2][NT][4]) {
#pragma unroll
    for (int mt = 0; mt < 2; mt++)
#pragma unroll
        for (int nt = 0; nt < NT; nt++)
#pragma unroll
            for (int q = 0; q < 4; q++) c[mt][nt][q] = 0.f;
#pragma unroll
    for (int ks = 0; ks < 8; ks++) {
        int k0 = ks * 16;
        unsigned af[2][4];
#pragma unroll
        for (int mt = 0; mt < 2; mt++) {
            const __nv_bfloat16* p = As + (wm * 32 + mt * 16 + gid) * SA + k0 + tig * 2;
            af[mt][0] = *(const unsigned*)(p);
            af[mt][1] = *(const unsigned*)(p + 8 * SA);
            af[mt][2] = *(const unsigned*)(p + 8);
            af[mt][3] = *(const unsigned*)(p + 8 * SA + 8);
        }
        unsigned bfr[NT][2];
#pragma unroll
        for (int nt = 0; nt < NT; nt++) {
            const __nv_bfloat16* q = Bs + (wn * (NT * 8) + nt * 8 + gid) * SA + k0 + tig * 2;
            bfr[nt][0] = *(const unsigned*)(q);
            bfr[nt][1] = *(const unsigned*)(q + 8);
        }
#pragma unroll
        for (int mt = 0; mt < 2; mt++)
#pragma unroll
            for (int nt = 0; nt < NT; nt++)
                mma16816(c[mt][nt], af[mt], bfr[nt]);
    }
}

// ---------------- GEMM1: xb = bf16(relu(aggb @ W1t^T + b1) * outnorm) ----------------
__global__ void __launch_bounds__(256) gemm1_kernel(
    const __nv_bfloat16* __restrict__ A, const __nv_bfloat16* __restrict__ Bt,
    const float* __restrict__ bias, const float* __restrict__ postscale,
    __nv_bfloat16* __restrict__ outp, int M)
{
    extern __shared__ char smem[];
    __nv_bfloat16* As = (__nv_bfloat16*)smem;
    __nv_bfloat16* Bs = (__nv_bfloat16*)(smem + 128 * SA * 2);
    float* bs = (float*)(smem + 2 * 128 * SA * 2);
    int tid = threadIdx.x;
    int brow = blockIdx.x * 128;

    for (int i = tid; i < 128 * 16; i += 256) {
        int row = i >> 4, seg = i & 15;
        uint4 v = make_uint4(0u, 0u, 0u, 0u);
        int gr = brow + row;
        if (gr < M) v = *(const uint4*)(A + (size_t)gr * 128 + seg * 8);
        *(uint4*)(As + row * SA + seg * 8) = v;
    }
    for (int i = tid; i < 128 * 16; i += 256) {
        int row = i >> 4, seg = i & 15;
        *(uint4*)(Bs + row * SA + seg * 8) = *(const uint4*)(Bt + (size_t)row * 128 + seg * 8);
    }
    if (tid < 128) bs[tid] = bias[tid];
    __syncthreads();

    int wid = tid >> 5, lane = tid & 31;
    int wm = wid & 3, wn = wid >> 2;
    int gid = lane >> 2, tig = lane & 3;

    float c[2][8][4];
    mma_stage<8>(As, Bs, wm, wn, gid, tig, c);

#pragma unroll
    for (int mt = 0; mt < 2; mt++) {
        int r0 = brow + wm * 32 + mt * 16 + gid;
        int r1 = r0 + 8;
        float p0 = (r0 < M) ? postscale[r0] : 1.f;
        float p1 = (r1 < M) ? postscale[r1] : 1.f;
#pragma unroll
        for (int nt = 0; nt < 8; nt++) {
            int col = wn * 64 + nt * 8 + tig * 2;
            float b0v = bs[col], b1v = bs[col + 1];
            float v0 = fmaxf(c[mt][nt][0] + b0v, 0.f) * p0;
            float v1 = fmaxf(c[mt][nt][1] + b1v, 0.f) * p0;
            float v2 = fmaxf(c[mt][nt][2] + b0v, 0.f) * p1;
            float v3 = fmaxf(c[mt][nt][3] + b1v, 0.f) * p1;
            if (r0 < M) {
                __nv_bfloat162 pk = __floats2bfloat162_rn(v0, v1);
                *(unsigned*)(outp + (size_t)r0 * 128 + col) = *reinterpret_cast<unsigned*>(&pk);
            }
            if (r1 < M) {
                __nv_bfloat162 pk = __floats2bfloat162_rn(v2, v3);
                *(unsigned*)(outp + (size_t)r1 * 128 + col) = *reinterpret_cast<unsigned*>(&pk);
            }
        }
    }
}

// ---------------- fused conv2-GEMM + MLP1 + MLP2 ----------------
// D1 = relu(aggb @ W2 + b2); D2 = relu(D1 @ Wm1 + bm1); out = sigmoid(D2 @ Wm2 + bm2)
__global__ void __launch_bounds__(256) fused3_kernel(
    const __nv_bfloat16* __restrict__ A,
    const __nv_bfloat16* __restrict__ W2t,
    const __nv_bfloat16* __restrict__ Wm1t,
    const __nv_bfloat16* __restrict__ Wm2t,
    const float* __restrict__ b2, const float* __restrict__ bm1, const float* __restrict__ bm2,
    float* __restrict__ outp, int M)
{
    extern __shared__ char smem[];
    __nv_bfloat16* As = (__nv_bfloat16*)smem;
    __nv_bfloat16* Bs = (__nv_bfloat16*)(smem + 128 * SA * 2);
    float* bs = (float*)(smem + 2 * 128 * SA * 2);   // [0:128)=b2, [128:256)=bm1, [256:320)=bm2
    int tid = threadIdx.x;
    int brow = blockIdx.x * 128;
    int wid = tid >> 5, lane = tid & 31;
    int wm = wid & 3, wn = wid >> 2;
    int gid = lane >> 2, tig = lane & 3;

    // stage 1 loads
    for (int i = tid; i < 128 * 16; i += 256) {
        int row = i >> 4, seg = i & 15;
        uint4 v = make_uint4(0u, 0u, 0u, 0u);
        int gr = brow + row;
        if (gr < M) v = *(const uint4*)(A + (size_t)gr * 128 + seg * 8);
        *(uint4*)(As + row * SA + seg * 8) = v;
    }
    for (int i = tid; i < 128 * 16; i += 256) {
        int row = i >> 4, seg = i & 15;
        *(uint4*)(Bs + row * SA + seg * 8) = *(const uint4*)(W2t + (size_t)row * 128 + seg * 8);
    }
    if (tid < 128) bs[tid] = b2[tid];
    else if (tid < 256) bs[tid] = bm1[tid - 128];
    if (tid < 64) bs[256 + tid] = bm2[tid];
    __syncthreads();

    float c[2][8][4];

    // ---- stage 1: D1 = relu(A @ W2 + b2) ----
    mma_stage<8>(As, Bs, wm, wn, gid, tig, c);
    __syncthreads();  // all reads of As/Bs done
#pragma unroll
    for (int mt = 0; mt < 2; mt++) {
        int r0l = wm * 32 + mt * 16 + gid;
#pragma unroll
        for (int nt = 0; nt < 8; nt++) {
            int col = wn * 64 + nt * 8 + tig * 2;
            float b0v = bs[col], b1v = bs[col + 1];
            __nv_bfloat162 pk0 = __floats2bfloat162_rn(
                fmaxf(c[mt][nt][0] + b0v, 0.f), fmaxf(c[mt][nt][1] + b1v, 0.f));
            __nv_bfloat162 pk1 = __floats2bfloat162_rn(
                fmaxf(c[mt][nt][2] + b0v, 0.f), fmaxf(c[mt][nt][3] + b1v, 0.f));
            *(unsigned*)(As + r0l * SA + col) = *reinterpret_cast<unsigned*>(&pk0);
            *(unsigned*)(As + (r0l + 8) * SA + col) = *reinterpret_cast<unsigned*>(&pk1);
        }
    }
    for (int i = tid; i < 128 * 16; i += 256) {
        int row = i >> 4, seg = i & 15;
        *(uint4*)(Bs + row * SA + seg * 8) = *(const uint4*)(Wm1t + (size_t)row * 128 + seg * 8);
    }
    __syncthreads();

    // ---- stage 2: D2 = relu(D1 @ Wm1 + bm1) ----
    mma_stage<8>(As, Bs, wm, wn, gid, tig, c);
    __syncthreads();
#pragma unroll
    for (int mt = 0; mt < 2; mt++) {
        int r0l = wm * 32 + mt * 16 + gid;
#pragma unroll
        for (int nt = 0; nt < 8; nt++) {
            int col = wn * 64 + nt * 8 + tig * 2;
            float b0v = bs[128 + col], b1v = bs[128 + col + 1];
            __nv_bfloat162 pk0 = __floats2bfloat162_rn(
                fmaxf(c[mt][nt][0] + b0v, 0.f), fmaxf(c[mt][nt][1] + b1v, 0.f));
            __nv_bfloat162 pk1 = __floats2bfloat162_rn(
                fmaxf(c[mt][nt][2] + b0v, 0.f), fmaxf(c[mt][nt][3] + b1v, 0.f));
            *(unsigned*)(As + r0l * SA + col) = *reinterpret_cast<unsigned*>(&pk0);
            *(unsigned*)(As + (r0l + 8) * SA + col) = *reinterpret_cast<unsigned*>(&pk1);
        }
    }
    for (int i = tid; i < 64 * 16; i += 256) {
        int row = i >> 4, seg = i & 15;
        *(uint4*)(Bs + row * SA + seg * 8) = *(const uint4*)(Wm2t + (size_t)row * 128 + seg * 8);
    }
    __syncthreads();

    // ---- stage 3: out = sigmoid(D2 @ Wm2 + bm2), N=64 ----
    float c3[2][4][4];
    mma_stage<4>(As, Bs, wm, wn, gid, tig, c3);
#pragma unroll
    for (int mt = 0; mt < 2; mt++) {
        int r0 = brow + wm * 32 + mt * 16 + gid;
        int r1 = r0 + 8;
#pragma unroll
        for (int nt = 0; nt < 4; nt++) {
            int col = wn * 32 + nt * 8 + tig * 2;
            float b0v = bs[256 + col], b1v = bs[256 + col + 1];
            float v0 = 1.f / (1.f + __expf(-(c3[mt][nt][0] + b0v)));
            float v1 = 1.f / (1.f + __expf(-(c3[mt][nt][1] + b1v)));
            float v2 = 1.f / (1.f + __expf(-(c3[mt][nt][2] + b0v)));
            float v3 = 1.f / (1.f + __expf(-(c3[mt][nt][3] + b1v)));
            if (r0 < M) *(float2*)(outp + (size_t)r0 * 64 + col) = make_float2(v0, v1);
            if (r1 < M) *(float2*)(outp + (size_t)r1 * 64 + col) = make_float2(v2, v3);
        }
    }
}

// ---------------- launch ----------------
extern "C" void kernel_launch(void* const* d_in, const int* in_sizes, int n_in,
                              void* d_out, int out_size) {
    const float* x   = (const float*)d_in[0];
    const int*   src = (const int*)d_in[1];
    const int*   dst = (const int*)d_in[2];
    const float* W1  = (const float*)d_in[3];
    const float* b1  = (const float*)d_in[4];
    const float* W2  = (const float*)d_in[5];
    const float* b2  = (const float*)d_in[6];
    const float* Wm1 = (const float*)d_in[7];
    const float* bm1 = (const float*)d_in[8];
    const float* Wm2 = (const float*)d_in[9];
    const float* bm2 = (const float*)d_in[10];
    float* out = (float*)d_out;

    void *p_xb, *p_aggb, *p_w1t, *p_w2t, *p_wm1t, *p_wm2t, *p_outnorm;
    cudaGetSymbolAddress(&p_xb, g_xb);
    cudaGetSymbolAddress(&p_aggb, g_aggb);
    cudaGetSymbolAddress(&p_w1t, g_w1t);
    cudaGetSymbolAddress(&p_w2t, g_w2t);
    cudaGetSymbolAddress(&p_wm1t, g_wm1t);
    cudaGetSymbolAddress(&p_wm2t, g_wm2t);
    cudaGetSymbolAddress(&p_outnorm, g_outnorm);

    constexpr int SMEM_G = 2 * 128 * SA * 2 + 1536;  // A + B + biases = 71168
    cudaFuncSetAttribute(gemm1_kernel, cudaFuncAttributeMaxDynamicSharedMemorySize, SMEM_G);
    cudaFuncSetAttribute(fused3_kernel, cudaFuncAttributeMaxDynamicSharedMemorySize, SMEM_G);

    const int TB = 256;
    int nblk = (NN + TB - 1) / TB;
    int e4blk = (EE / 4 + TB - 1) / TB;
    int sblk = (NN + 1023) / 1024;  // 98
    int gblk = (NN + 127) / 128;    // 782
    int ablk = (NN * 32 + TB - 1) / TB;

    // graph preprocessing
    zero_kernel<<<nblk, TB>>>();
    degree_kernel<<<e4blk, TB>>>((const int4*)src, (const int4*)dst);
    scan_reduce_kernel<<<sblk, 256>>>();
    scan_partials_kernel<<<1, 128>>>(sblk);
    scan_down_kernel<<<sblk, 1024>>>();
    fill_kernel<<<e4blk, TB>>>((const int4*)src, (const int4*)dst);

    // weights
    wt_kernel<<<(57344 + TB - 1) / TB, TB>>>(W1, W2, Wm1, Wm2);

    // conv1
    agg1_kernel<<<ablk, TB>>>((const float4*)x);
    gemm1_kernel<<<gblk, 256, SMEM_G>>>(
        (const __nv_bfloat16*)p_aggb, (const __nv_bfloat16*)p_w1t, b1,
        (const float*)p_outnorm, (__nv_bfloat16*)p_xb, NN);

    // conv2 + MLP (fused)
    agg2_kernel<<<ablk, TB>>>();
    fused3_kernel<<<gblk, 256, SMEM_G>>>(
        (const __nv_bfloat16*)p_aggb,
        (const __nv_bfloat16*)p_w2t, (const __nv_bfloat16*)p_wm1t, (const __nv_bfloat16*)p_wm2t,
        b2, bm1, bm2, out, NN);
}